// round 5
// baseline (speedup 1.0000x reference)
#include <cuda_runtime.h>
#include <cuda_bf16.h>

#define NN 50000
#define EE 1000000
#define C 64

// ---------------- static scratch ----------------
__device__ float g_hw[NN * C];   // h = x @ W (pre-activation features)
__device__ float g_h[NN * C];    // layer output (post relu)
__device__ float g_A[NN * C];    // h2 @ Wm1[0:64]
__device__ float g_B[NN * C];    // h2 @ Wm1[65:129]
__device__ float g_al[NN];
__device__ float g_ar[NN];
__device__ int   g_src[EE];
__device__ int   g_dst[EE];
__device__ int   g_deg[NN];
__device__ int   g_ptr[NN];
__device__ int   g_cur[NN];
__device__ int   g_csrc[EE];     // CSR: src node per slot (grouped by dst)
__device__ int   g_ceid[EE];     // CSR: original edge id per slot
__device__ int   g_part[256];
__device__ int   g_poff[256];
__device__ int   g_i32flag;

// ---------------- init: zero degree histogram + flag ----------------
__global__ void reset_kernel(int n) {
    int i = blockIdx.x * blockDim.x + threadIdx.x;
    if (i < n) g_deg[i] = 0;
    if (i == 0) g_i32flag = 0;
}

// int64 edge_index (values < 2^31, little-endian) => all odd words are 0
__global__ void detect_kernel(const int* __restrict__ w, int nwords_half) {
    int t = blockIdx.x * blockDim.x + threadIdx.x;
    if (t >= nwords_half) return;
    if (w[2 * t + 1] != 0) atomicOr(&g_i32flag, 1);
}

// convert to int32 + degree histogram (by dst)
__global__ void conv_hist_kernel(const void* __restrict__ ei, int E) {
    int e = blockIdx.x * blockDim.x + threadIdx.x;
    if (e >= E) return;
    int s, d;
    if (g_i32flag == 0) {
        const long long* p = (const long long*)ei;
        s = (int)p[e]; d = (int)p[(size_t)E + e];
    } else {
        const int* p = (const int*)ei;
        s = p[e]; d = p[E + e];
    }
    g_src[e] = s;
    g_dst[e] = d;
    atomicAdd(g_deg + d, 1);
}

// ---------------- 3-kernel exclusive scan over g_deg -> g_ptr ----------------
__global__ __launch_bounds__(256) void scan1_kernel(int n) {
    __shared__ int sh[256];
    int i = blockIdx.x * 256 + threadIdx.x;
    int v = (i < n) ? g_deg[i] : 0;
    sh[threadIdx.x] = v;
    __syncthreads();
    for (int o = 128; o; o >>= 1) {
        if (threadIdx.x < o) sh[threadIdx.x] += sh[threadIdx.x + o];
        __syncthreads();
    }
    if (threadIdx.x == 0) g_part[blockIdx.x] = sh[0];
}

__global__ __launch_bounds__(256) void scan2_kernel(int P) {
    __shared__ int sh[256];
    int t = threadIdx.x;
    int v = (t < P) ? g_part[t] : 0;
    sh[t] = v;
    __syncthreads();
    // inclusive Hillis-Steele
    for (int o = 1; o < 256; o <<= 1) {
        int add = (t >= o) ? sh[t - o] : 0;
        __syncthreads();
        sh[t] += add;
        __syncthreads();
    }
    if (t < P) g_poff[t] = sh[t] - v;   // exclusive
}

__global__ __launch_bounds__(256) void scan3_kernel(int n) {
    __shared__ int sh[256];
    int t = threadIdx.x;
    int i = blockIdx.x * 256 + t;
    int v = (i < n) ? g_deg[i] : 0;
    sh[t] = v;
    __syncthreads();
    for (int o = 1; o < 256; o <<= 1) {
        int add = (t >= o) ? sh[t - o] : 0;
        __syncthreads();
        sh[t] += add;
        __syncthreads();
    }
    if (i < n) {
        int excl = sh[t] - v + g_poff[blockIdx.x];
        g_ptr[i] = excl;
        g_cur[i] = excl;
    }
}

__global__ void scatter_kernel(int E) {
    int e = blockIdx.x * blockDim.x + threadIdx.x;
    if (e >= E) return;
    int d = g_dst[e];
    int pos = atomicAdd(g_cur + d, 1);
    g_csrc[pos] = g_src[e];
    g_ceid[pos] = e;
}

// ---------------- 64x64 GEMM: g_hw = X @ W, pipelined register blocking ----------
__global__ __launch_bounds__(256) void gemm64_kernel(
    const float* __restrict__ Xext, const float* __restrict__ W, int inSel, int n)
{
    __shared__ float Xs[C * C];   // Xs[k*64 + r] (transposed)
    __shared__ float Ws[C * C];   // Ws[k*64 + c]
    const float* X = inSel ? g_h : Xext;

    int tid = threadIdx.x;
    int row0 = blockIdx.x * 64;

    for (int i = tid; i < C * C; i += 256) Ws[i] = W[i];
    for (int i = tid; i < 64 * 16; i += 256) {
        int r = i >> 4;
        int k4 = (i & 15) * 4;
        int gr = row0 + r;
        float4 v = (gr < n) ? *(const float4*)(X + (size_t)gr * C + k4)
                            : make_float4(0.f, 0.f, 0.f, 0.f);
        Xs[(k4 + 0) * C + r] = v.x;
        Xs[(k4 + 1) * C + r] = v.y;
        Xs[(k4 + 2) * C + r] = v.z;
        Xs[(k4 + 3) * C + r] = v.w;
    }
    __syncthreads();

    int tx = tid & 15, ty = tid >> 4;
    const float* xp = Xs + ty * 4;
    const float* wp = Ws + tx * 4;
    float acc[4][4] = {};
    float4 xa0 = *(const float4*)(xp);
    float4 wb0 = *(const float4*)(wp);
    float4 xa1 = *(const float4*)(xp + C);
    float4 wb1 = *(const float4*)(wp + C);
    #pragma unroll
    for (int k = 0; k < C; k++) {
        float4 xn, wn;
        if (k + 2 < C) {
            xn = *(const float4*)(xp + (k + 2) * C);
            wn = *(const float4*)(wp + (k + 2) * C);
        }
        acc[0][0] += xa0.x * wb0.x; acc[0][1] += xa0.x * wb0.y; acc[0][2] += xa0.x * wb0.z; acc[0][3] += xa0.x * wb0.w;
        acc[1][0] += xa0.y * wb0.x; acc[1][1] += xa0.y * wb0.y; acc[1][2] += xa0.y * wb0.z; acc[1][3] += xa0.y * wb0.w;
        acc[2][0] += xa0.z * wb0.x; acc[2][1] += xa0.z * wb0.y; acc[2][2] += xa0.z * wb0.z; acc[2][3] += xa0.z * wb0.w;
        acc[3][0] += xa0.w * wb0.x; acc[3][1] += xa0.w * wb0.y; acc[3][2] += xa0.w * wb0.z; acc[3][3] += xa0.w * wb0.w;
        xa0 = xa1; wb0 = wb1; xa1 = xn; wb1 = wn;
    }
    #pragma unroll
    for (int i = 0; i < 4; i++) {
        int r = row0 + ty * 4 + i;
        if (r < n)
            *(float4*)(g_hw + (size_t)r * C + tx * 4) =
                make_float4(acc[i][0], acc[i][1], acc[i][2], acc[i][3]);
    }
}

// -------- fused A/B GEMM: g_A = g_h @ Wm1[0:64], g_B = g_h @ Wm1[65:129] --------
__global__ __launch_bounds__(512) void gemmAB_kernel(
    const float* __restrict__ Wa, const float* __restrict__ Wb, int n)
{
    __shared__ float Xs[C * C];       // 16 KB, transposed
    __shared__ float Ws[C * 128];     // 32 KB: [k][c], c<64 -> Wa, c>=64 -> Wb
    int tid = threadIdx.x;
    int row0 = blockIdx.x * 64;

    for (int i = tid; i < C * 128; i += 512) {
        int k = i >> 7, c = i & 127;
        Ws[i] = (c < 64) ? Wa[k * 64 + c] : Wb[k * 64 + (c - 64)];
    }
    for (int i = tid; i < 64 * 16; i += 512) {
        int r = i >> 4;
        int k4 = (i & 15) * 4;
        int gr = row0 + r;
        float4 v = (gr < n) ? *(const float4*)(g_h + (size_t)gr * C + k4)
                            : make_float4(0.f, 0.f, 0.f, 0.f);
        Xs[(k4 + 0) * C + r] = v.x;
        Xs[(k4 + 1) * C + r] = v.y;
        Xs[(k4 + 2) * C + r] = v.z;
        Xs[(k4 + 3) * C + r] = v.w;
    }
    __syncthreads();

    int tx = tid & 31, ty = tid >> 5;        // tx: 32 col-groups, ty: 16 row-groups
    const float* xp = Xs + ty * 4;
    const float* wp = Ws + tx * 4;
    float acc[4][4] = {};
    float4 xa0 = *(const float4*)(xp);
    float4 wb0 = *(const float4*)(wp);
    float4 xa1 = *(const float4*)(xp + C);
    float4 wb1 = *(const float4*)(wp + 128);
    #pragma unroll
    for (int k = 0; k < C; k++) {
        float4 xn, wn;
        if (k + 2 < C) {
            xn = *(const float4*)(xp + (k + 2) * C);
            wn = *(const float4*)(wp + (k + 2) * 128);
        }
        acc[0][0] += xa0.x * wb0.x; acc[0][1] += xa0.x * wb0.y; acc[0][2] += xa0.x * wb0.z; acc[0][3] += xa0.x * wb0.w;
        acc[1][0] += xa0.y * wb0.x; acc[1][1] += xa0.y * wb0.y; acc[1][2] += xa0.y * wb0.z; acc[1][3] += xa0.y * wb0.w;
        acc[2][0] += xa0.z * wb0.x; acc[2][1] += xa0.z * wb0.y; acc[2][2] += xa0.z * wb0.z; acc[2][3] += xa0.z * wb0.w;
        acc[3][0] += xa0.w * wb0.x; acc[3][1] += xa0.w * wb0.y; acc[3][2] += xa0.w * wb0.z; acc[3][3] += xa0.w * wb0.w;
        xa0 = xa1; wb0 = wb1; xa1 = xn; wb1 = wn;
    }
    int col = tx * 4;
    float* Y = (col < 64) ? g_A : g_B;
    int cc = col & 63;
    #pragma unroll
    for (int i = 0; i < 4; i++) {
        int r = row0 + ty * 4 + i;
        if (r < n)
            *(float4*)(Y + (size_t)r * C + cc) =
                make_float4(acc[i][0], acc[i][1], acc[i][2], acc[i][3]);
    }
}

// ---------------- per-node attention dots ----------------
__global__ __launch_bounds__(256) void attdot_kernel(
    const float* __restrict__ attL, const float* __restrict__ attR, int n)
{
    int node = (blockIdx.x * blockDim.x + threadIdx.x) >> 4;
    int lane = threadIdx.x & 15;
    if (node >= n) return;
    float4 h = ((const float4*)(g_hw + (size_t)node * C))[lane];
    float4 aL = ((const float4*)attL)[lane];
    float4 aR = ((const float4*)attR)[lane];
    float dl = h.x * aL.x + h.y * aL.y + h.z * aL.z + h.w * aL.w;
    float dr = h.x * aR.x + h.y * aR.y + h.z * aR.z + h.w * aR.w;
    #pragma unroll
    for (int o = 8; o; o >>= 1) {
        dl += __shfl_xor_sync(0xffffffffu, dl, o);
        dr += __shfl_xor_sync(0xffffffffu, dr, o);
    }
    if (lane == 0) { g_al[node] = dl; g_ar[node] = dr; }
}

// ------- CSR aggregation: warp per dst node; fused self-loop + norm + bias + relu -------
__global__ __launch_bounds__(256) void agg_kernel(const float* __restrict__ bias, int n)
{
    int node = (blockIdx.x * blockDim.x + threadIdx.x) >> 5;
    int lane = threadIdx.x & 31;
    if (node >= n) return;
    float2 hi = ((const float2*)(g_hw + (size_t)node * C))[lane];
    float dd = hi.x * hi.x + hi.y * hi.y;
    #pragma unroll
    for (int o = 16; o; o >>= 1) dd += __shfl_xor_sync(0xffffffffu, dd, o);
    float al_i = __ldg(g_al + node);
    float ar_i = __ldg(g_ar + node);
    // self-loop
    float a = (al_i + ar_i) / (1.f + __expf(-dd));
    a = (a > 0.f) ? a : 0.2f * a;
    float ex = __expf(a);
    float2 acc = make_float2(hi.x * ex, hi.y * ex);
    float s = ex;

    int p = __ldg(g_ptr + node);
    int pe = p + __ldg(g_deg + node);
    int jn = (p < pe) ? __ldg(g_csrc + p) : 0;
    for (; p < pe; p++) {
        int j = jn;
        if (p + 1 < pe) jn = __ldg(g_csrc + p + 1);
        float2 hj = ((const float2*)(g_hw + (size_t)j * C))[lane];
        float d = hj.x * hi.x + hj.y * hi.y;
        #pragma unroll
        for (int o = 16; o; o >>= 1) d += __shfl_xor_sync(0xffffffffu, d, o);
        float aa = (__ldg(g_al + j) + ar_i) / (1.f + __expf(-d));
        aa = (aa > 0.f) ? aa : 0.2f * aa;
        float e2 = __expf(aa);
        acc.x += hj.x * e2;
        acc.y += hj.y * e2;
        s += e2;
    }
    float2 bb = ((const float2*)bias)[lane];
    float inv = 1.f / s;
    float vx = acc.x * inv + bb.x;
    float vy = acc.y * inv + bb.y;
    ((float2*)(g_h + (size_t)node * C))[lane] =
        make_float2(vx > 0.f ? vx : 0.f, vy > 0.f ? vy : 0.f);
}

// ------- CSR edge MLP: warp per dst node; B[dst] cached, gather A[src] -------
__global__ __launch_bounds__(256) void mlp_kernel(
    const float* __restrict__ edge_attr,
    const float* __restrict__ Wm1row64,
    const float* __restrict__ bm1,
    const float* __restrict__ Wm2,
    const float* __restrict__ bm2,
    float* __restrict__ out, int n)
{
    int node = (blockIdx.x * blockDim.x + threadIdx.x) >> 5;
    int lane = threadIdx.x & 31;
    if (node >= n) return;
    float2 Bv = ((const float2*)(g_B + (size_t)node * C))[lane];
    float2 we = ((const float2*)Wm1row64)[lane];
    float2 bb = ((const float2*)bm1)[lane];
    float2 w2 = ((const float2*)Wm2)[lane];
    float bm2v = __ldg(bm2);
    float base_x = Bv.x + bb.x;
    float base_y = Bv.y + bb.y;

    int p = __ldg(g_ptr + node);
    int pe = p + __ldg(g_deg + node);
    for (; p < pe; p++) {
        int j = __ldg(g_csrc + p);
        int eid = __ldg(g_ceid + p);
        float ea = __ldg(edge_attr + eid);
        float2 Av = ((const float2*)(g_A + (size_t)j * C))[lane];
        float tx = Av.x + base_x + ea * we.x; tx = (tx > 0.f) ? tx : 0.f;
        float ty = Av.y + base_y + ea * we.y; ty = (ty > 0.f) ? ty : 0.f;
        float d = tx * w2.x + ty * w2.y;
        #pragma unroll
        for (int o = 16; o; o >>= 1) d += __shfl_xor_sync(0xffffffffu, d, o);
        if (lane == 0) out[eid] = d + bm2v;
    }
}

// ---------------- launcher ----------------
extern "C" void kernel_launch(void* const* d_in, const int* in_sizes, int n_in,
                              void* d_out, int out_size)
{
    const float* x     = (const float*)d_in[0];
    const void*  ei    = d_in[1];
    const float* ea    = (const float*)d_in[2];
    const float* W1    = (const float*)d_in[3];
    const float* attL1 = (const float*)d_in[4];
    const float* attR1 = (const float*)d_in[5];
    const float* b1    = (const float*)d_in[6];
    const float* W2    = (const float*)d_in[7];
    const float* attL2 = (const float*)d_in[8];
    const float* attR2 = (const float*)d_in[9];
    const float* b2    = (const float*)d_in[10];
    const float* Wm1   = (const float*)d_in[11];
    const float* bm1   = (const float*)d_in[12];
    const float* Wm2   = (const float*)d_in[13];
    const float* bm2   = (const float*)d_in[14];
    float* out = (float*)d_out;

    int n = in_sizes[0] / C;
    int E = in_sizes[2];

    const int TB = 256;
    int nodeBlocks = (n + TB - 1) / TB;            // 196
    int edgeBlocks = (E + TB - 1) / TB;
    int gemmGrid   = (n + 63) / 64;
    int dotGrid    = (n * 16 + TB - 1) / TB;
    int warpGrid   = (n * 32 + TB - 1) / TB;       // warp per node

    // ---- CSR build ----
    reset_kernel<<<nodeBlocks, TB>>>(n);
    detect_kernel<<<edgeBlocks, TB>>>((const int*)ei, E);
    conv_hist_kernel<<<edgeBlocks, TB>>>(ei, E);
    scan1_kernel<<<nodeBlocks, TB>>>(n);
    scan2_kernel<<<1, TB>>>(nodeBlocks);
    scan3_kernel<<<nodeBlocks, TB>>>(n);
    scatter_kernel<<<edgeBlocks, TB>>>(E);

    // ---- Layer 1 ----
    gemm64_kernel<<<gemmGrid, TB>>>(x, W1, 0, n);
    attdot_kernel<<<dotGrid, TB>>>(attL1, attR1, n);
    agg_kernel<<<warpGrid, TB>>>(b1, n);

    // ---- Layer 2 ----
    gemm64_kernel<<<gemmGrid, TB>>>(nullptr, W2, 1, n);
    attdot_kernel<<<dotGrid, TB>>>(attL2, attR2, n);
    agg_kernel<<<warpGrid, TB>>>(b2, n);

    // ---- Edge MLP ----
    gemmAB_kernel<<<gemmGrid, 512>>>(Wm1, Wm1 + 65 * C, n);
    mlp_kernel<<<warpGrid, TB>>>(ea, Wm1 + 64 * C, bm1, Wm2, bm2, out, n);
}